// round 4
// baseline (speedup 1.0000x reference)
#include <cuda_runtime.h>
#include <cuda_bf16.h>

// Off-diagonal Gram sum via:
//   (1/D) sum_d [ (sum_b x2[b,d])^2 - sum_b x2[b,d]^2 ],  x2 = x*x.
//
// R4: split b-dimension 4-ways across lane groups (lane = 8q + c). Each
// thread loads 8 b-rows of one float4 column; full per-column sum s is
// recovered with two shfl_xor butterflies. 4x more warps (32/SM) to hide
// DRAM latency — R3 was latency-bound at occ=9.7%, DRAM=28%.

#define B_ROWS 32
#define THREADS 256
#define SPLIT 4
#define BPT (B_ROWS / SPLIT)   // 8 b-rows per thread

__device__ double g_acc = 0.0;
__device__ unsigned int g_count = 0;

__global__ void __launch_bounds__(THREADS, 4)
ortho_fused_kernel(const float4* __restrict__ in,
                   float* __restrict__ out,
                   int d4, double inv_d) {
    int gtid   = blockIdx.x * THREADS + threadIdx.x;
    int gwid   = gtid >> 5;            // global warp id
    int lane   = threadIdx.x & 31;
    int q      = lane >> 3;            // b-quarter (0..3)
    int c      = lane & 7;             // column-chunk within warp (0..7)
    int col    = gwid * 8 + c;         // float4 column in [0, d4)

    float4 v[BPT];
    bool valid = (col < d4);
    const float4* p = in + (size_t)(q * BPT) * d4 + col;
    #pragma unroll
    for (int j = 0; j < BPT; j++) {
        if (valid) v[j] = p[(size_t)j * d4];
        else       v[j] = make_float4(0.f, 0.f, 0.f, 0.f);
    }

    float s0 = 0.f, s1 = 0.f, s2 = 0.f, s3 = 0.f, t = 0.f;
    #pragma unroll
    for (int j = 0; j < BPT; j++) {
        float a0 = v[j].x * v[j].x;
        float a1 = v[j].y * v[j].y;
        float a2 = v[j].z * v[j].z;
        float a3 = v[j].w * v[j].w;
        s0 += a0; t = fmaf(a0, a0, t);
        s1 += a1; t = fmaf(a1, a1, t);
        s2 += a2; t = fmaf(a2, a2, t);
        s3 += a3; t = fmaf(a3, a3, t);
    }

    // Recover full column sums s across the 4 b-quarters (lanes c, c+8, c+16, c+24).
    s0 += __shfl_xor_sync(0xFFFFFFFFu, s0, 8);
    s0 += __shfl_xor_sync(0xFFFFFFFFu, s0, 16);
    s1 += __shfl_xor_sync(0xFFFFFFFFu, s1, 8);
    s1 += __shfl_xor_sync(0xFFFFFFFFu, s1, 16);
    s2 += __shfl_xor_sync(0xFFFFFFFFu, s2, 8);
    s2 += __shfl_xor_sync(0xFFFFFFFFu, s2, 16);
    s3 += __shfl_xor_sync(0xFFFFFFFFu, s3, 8);
    s3 += __shfl_xor_sync(0xFFFFFFFFu, s3, 16);

    // t is additive (every lane contributes its own partial); s^2 counted once (q==0).
    float cpart = -t;
    if (q == 0) cpart += (s0 * s0 + s1 * s1) + (s2 * s2 + s3 * s3);
    double contrib = (double)cpart;

    // warp reduction (doubles)
    #pragma unroll
    for (int off = 16; off > 0; off >>= 1)
        contrib += __shfl_down_sync(0xFFFFFFFFu, contrib, off);

    __shared__ double warp_sums[THREADS / 32];
    int wid = threadIdx.x >> 5;
    if (lane == 0) warp_sums[wid] = contrib;
    __syncthreads();

    if (threadIdx.x == 0) {
        double blk = 0.0;
        #pragma unroll
        for (int w = 0; w < THREADS / 32; w++) blk += warp_sums[w];
        atomicAdd(&g_acc, blk);
        __threadfence();
        unsigned int ticket = atomicAdd(&g_count, 1u);
        if (ticket == gridDim.x - 1) {
            out[0] = (float)(g_acc * inv_d);
            g_acc = 0.0;     // reset for next graph replay
            g_count = 0u;
        }
    }
}

extern "C" void kernel_launch(void* const* d_in, const int* in_sizes, int n_in,
                              void* d_out, int out_size) {
    const float4* in = (const float4*)d_in[0];
    float* out = (float*)d_out;

    int total = in_sizes[0];           // 32 * 150528
    int D = total / B_ROWS;            // 150528
    int d4 = D / 4;                    // 37632

    // one thread per (float4 column, b-quarter): d4 * 4 threads
    int n_threads = d4 * SPLIT;                        // 150528
    int blocks = (n_threads + THREADS - 1) / THREADS;  // 588
    ortho_fused_kernel<<<blocks, THREADS>>>(in, out, d4, 1.0 / (double)D);
}